// round 3
// baseline (speedup 1.0000x reference)
#include <cuda_runtime.h>

#define NN 100000
#define EE 600000

// ---------------- scratch (static device globals; no allocation) -------------
__device__ int   g_deg[NN];
__device__ int   g_off[NN + 1];
__device__ int   g_cur[NN];
__device__ float g_inv[NN];
__device__ int   g_src[EE];
__device__ float g_agg[(size_t)NN * 128];
__device__ float g_h[(size_t)NN * 128];
__device__ int   g_is64;

// ---------------- helpers ----------------------------------------------------
__device__ __forceinline__ unsigned long long pack2(float lo, float hi) {
    unsigned long long r;
    asm("mov.b64 %0, {%1, %2};" : "=l"(r) : "f"(lo), "f"(hi));
    return r;
}
__device__ __forceinline__ void unpack2(unsigned long long v, float& lo, float& hi) {
    asm("mov.b64 {%0, %1}, %2;" : "=f"(lo), "=f"(hi) : "l"(v));
}
__device__ __forceinline__ void fma2(unsigned long long& acc, unsigned long long a,
                                     unsigned long long b) {
    asm("fma.rn.f32x2 %0, %1, %2, %0;" : "+l"(acc) : "l"(a), "l"(b));
}

__device__ __forceinline__ int load_idx(const void* ei, long long pos, int is64) {
    if (is64) return (int)((const long long*)ei)[pos];
    return ((const int*)ei)[pos];
}

// ---------------- dtype detection: int64 vs int32 edge_index -----------------
__global__ void k_detect(const unsigned long long* ei) {
    if (threadIdx.x == 0 && blockIdx.x == 0) {
        int is64 = 1;
        #pragma unroll 1
        for (int i = 0; i < 64; i++)
            if (ei[i] > 0xFFFFFFFFull) is64 = 0;
        g_is64 = is64;
    }
}

// ---------------- degree histogram -------------------------------------------
__global__ void k_zero_deg() {
    int i = blockIdx.x * blockDim.x + threadIdx.x;
    if (i < NN) g_deg[i] = 0;
}

__global__ void k_deg(const void* ei) {
    int e = blockIdx.x * blockDim.x + threadIdx.x;
    if (e < EE) {
        int is64 = g_is64;
        int dst = load_idx(ei, (long long)EE + e, is64);
        atomicAdd(&g_deg[dst], 1);
    }
}

// ---------------- single-block chunked exclusive scan + inv_deg --------------
__global__ void k_scan() {
    __shared__ int s[1024];
    __shared__ int carry_s;
    int tid = threadIdx.x;
    if (tid == 0) carry_s = 0;
    __syncthreads();
    for (int base = 0; base < NN; base += 1024) {
        int i = base + tid;
        int v = (i < NN) ? g_deg[i] : 0;
        s[tid] = v;
        __syncthreads();
        #pragma unroll
        for (int d = 1; d < 1024; d <<= 1) {
            int t = (tid >= d) ? s[tid - d] : 0;
            __syncthreads();
            s[tid] += t;
            __syncthreads();
        }
        int carry = carry_s;
        if (i < NN) {
            int excl = carry + s[tid] - v;
            g_off[i] = excl;
            g_cur[i] = excl;
            g_inv[i] = 1.0f / (float)max(v, 1);
        }
        __syncthreads();
        if (tid == 1023) carry_s = carry + s[1023];
        __syncthreads();
    }
    if (tid == 0) g_off[NN] = EE;
}

// ---------------- CSR placement ----------------------------------------------
__global__ void k_fill(const void* ei) {
    int e = blockIdx.x * blockDim.x + threadIdx.x;
    if (e < EE) {
        int is64 = g_is64;
        int dst = load_idx(ei, (long long)EE + e, is64);
        int src = load_idx(ei, e, is64);
        int pos = atomicAdd(&g_cur[dst], 1);
        g_src[pos] = src;
    }
}

// ---------------- gather aggregation: warp per node, pre-scaled by inv_deg ---
__global__ void k_agg(const float* __restrict__ feat, float* __restrict__ agg) {
    int w = (blockIdx.x * blockDim.x + threadIdx.x) >> 5;
    int lane = threadIdx.x & 31;
    if (w >= NN) return;
    int s = g_off[w], e = g_off[w + 1];
    float4 acc = make_float4(0.f, 0.f, 0.f, 0.f);
    for (int i = s; i < e; i++) {
        int sn = g_src[i];
        float4 v = __ldg((const float4*)(feat + (size_t)sn * 128 + lane * 4));
        acc.x += v.x; acc.y += v.y; acc.z += v.z; acc.w += v.w;
    }
    float iv = g_inv[w];
    acc.x *= iv; acc.y *= iv; acc.z *= iv; acc.w *= iv;
    *((float4*)(agg + (size_t)w * 128 + lane * 4)) = acc;
}

// ---------------- fused SGEMM:  out = [Aagg | Ax] @ [Wl ; Wr] + bias ---------
// K is fixed at 256 (128 from agg side, 128 from x side). BN == ncols.
template <int BM, int BN, int BK, int TM, int TN, bool RELU>
__global__ void __launch_bounds__((BM / TM) * (BN / TN))
k_gemm(const float* __restrict__ Aagg, const float* __restrict__ Ax,
       const float* __restrict__ Wl, const float* __restrict__ Wr,
       const float* __restrict__ bias, float* __restrict__ outp,
       int nrows, int ncols) {
    constexpr int THREADS = (BM / TM) * (BN / TN);
    __shared__ float As[BK][BM];
    __shared__ float Bs[BK][BN];

    const int tid = threadIdx.x;
    const int row0 = blockIdx.x * BM;
    const int tcol = tid % (BN / TN);
    const int trow = tid / (BN / TN);

    unsigned long long acc[TM][TN / 2];
    #pragma unroll
    for (int m = 0; m < TM; m++)
        #pragma unroll
        for (int n = 0; n < TN / 2; n++) acc[m][n] = 0ull;

    #pragma unroll 1
    for (int kt = 0; kt < 256 / BK; kt++) {
        const int k0 = kt * BK;
        const float* Ap = (k0 < 128) ? (Aagg + k0) : (Ax + (k0 - 128));
        const float* Bp = (k0 < 128) ? (Wl + (size_t)k0 * ncols)
                                     : (Wr + (size_t)(k0 - 128) * ncols);
        // load A tile (transpose into As[k][m])
        #pragma unroll
        for (int t = 0; t < (BM * BK / 4) / THREADS; t++) {
            int id = tid + t * THREADS;
            int m = id / (BK / 4);
            int kq = (id % (BK / 4)) * 4;
            int row = row0 + m;
            float4 v = make_float4(0.f, 0.f, 0.f, 0.f);
            if (row < nrows) v = *(const float4*)(Ap + (size_t)row * 128 + kq);
            As[kq + 0][m] = v.x;
            As[kq + 1][m] = v.y;
            As[kq + 2][m] = v.z;
            As[kq + 3][m] = v.w;
        }
        // load B tile
        #pragma unroll
        for (int t = 0; t < (BK * BN / 4) / THREADS; t++) {
            int id = tid + t * THREADS;
            int k = id / (BN / 4);
            int jq = (id % (BN / 4)) * 4;
            *(float4*)&Bs[k][jq] = *(const float4*)(Bp + (size_t)k * ncols + jq);
        }
        __syncthreads();

        #pragma unroll
        for (int kk = 0; kk < BK; kk++) {
            float a[TM];
            #pragma unroll
            for (int i = 0; i < TM / 4; i++)
                *(float4*)&a[i * 4] = *(const float4*)&As[kk][trow * TM + i * 4];
            unsigned long long bq[TN / 2];
            #pragma unroll
            for (int i = 0; i < TN / 2; i++)
                bq[i] = *(const unsigned long long*)&Bs[kk][tcol * TN + i * 2];
            #pragma unroll
            for (int m = 0; m < TM; m++) {
                unsigned long long aa = pack2(a[m], a[m]);
                #pragma unroll
                for (int n = 0; n < TN / 2; n++) fma2(acc[m][n], aa, bq[n]);
            }
        }
        __syncthreads();
    }

    // epilogue: bias (+ relu) + store
    float bv[TN];
    #pragma unroll
    for (int n = 0; n < TN; n++) bv[n] = bias[tcol * TN + n];

    #pragma unroll
    for (int m = 0; m < TM; m++) {
        int row = row0 + trow * TM + m;
        if (row < nrows) {
            float vals[TN];
            #pragma unroll
            for (int n = 0; n < TN / 2; n++)
                unpack2(acc[m][n], vals[2 * n], vals[2 * n + 1]);
            #pragma unroll
            for (int n = 0; n < TN; n++) {
                vals[n] += bv[n];
                if (RELU) vals[n] = fmaxf(vals[n], 0.f);
            }
            #pragma unroll
            for (int n = 0; n < TN / 4; n++)
                *(float4*)(outp + (size_t)row * ncols + tcol * TN + n * 4) =
                    *(float4*)&vals[n * 4];
        }
    }
}

// ---------------- launch ------------------------------------------------------
extern "C" void kernel_launch(void* const* d_in, const int* in_sizes, int n_in,
                              void* d_out, int out_size) {
    const float* x   = (const float*)d_in[0];
    const void*  ei  = d_in[1];
    const float* W1l = (const float*)d_in[2];
    const float* b1  = (const float*)d_in[3];
    const float* W1r = (const float*)d_in[4];
    const float* W2l = (const float*)d_in[5];
    const float* b2  = (const float*)d_in[6];
    const float* W2r = (const float*)d_in[7];
    float* out = (float*)d_out;

    float *agg, *h;
    cudaGetSymbolAddress((void**)&agg, g_agg);
    cudaGetSymbolAddress((void**)&h, g_h);

    k_detect<<<1, 32>>>((const unsigned long long*)ei);
    k_zero_deg<<<(NN + 255) / 256, 256>>>();
    k_deg<<<(EE + 255) / 256, 256>>>(ei);
    k_scan<<<1, 1024>>>();
    k_fill<<<(EE + 255) / 256, 256>>>(ei);

    // layer 1
    k_agg<<<(NN * 32 + 255) / 256, 256>>>(x, agg);
    k_gemm<128, 128, 16, 8, 8, true>
        <<<(NN + 127) / 128, 256>>>(agg, x, W1l, W1r, b1, h, NN, 128);

    // layer 2
    k_agg<<<(NN * 32 + 255) / 256, 256>>>(h, agg);
    k_gemm<128, 32, 32, 8, 4, false>
        <<<(NN + 127) / 128, 128>>>(agg, h, W2l, W2r, b2, out, NN, 32);
}

// round 4
// speedup vs baseline: 1.3995x; 1.3995x over previous
#include <cuda_runtime.h>

#define NN 100000
#define EE 600000
#define SCAN_BLK 1024
#define NBLK ((NN + SCAN_BLK - 1) / SCAN_BLK)   // 98

// ---------------- scratch (static device globals; no allocation) -------------
__device__ int   g_deg[NN];
__device__ int   g_off[NN + 1];
__device__ int   g_cur[NN];
__device__ float g_inv[NN];
__device__ int   g_src[EE];
__device__ int   g_bsum[NBLK];
__device__ float g_agg[(size_t)NN * 128];
__device__ float g_h[(size_t)NN * 128];
__device__ int   g_is64;

// ---------------- helpers ----------------------------------------------------
__device__ __forceinline__ unsigned long long pack2(float lo, float hi) {
    unsigned long long r;
    asm("mov.b64 %0, {%1, %2};" : "=l"(r) : "f"(lo), "f"(hi));
    return r;
}
__device__ __forceinline__ void unpack2(unsigned long long v, float& lo, float& hi) {
    asm("mov.b64 {%0, %1}, %2;" : "=f"(lo), "=f"(hi) : "l"(v));
}
__device__ __forceinline__ void fma2(unsigned long long& acc, unsigned long long a,
                                     unsigned long long b) {
    asm("fma.rn.f32x2 %0, %1, %2, %0;" : "+l"(acc) : "l"(a), "l"(b));
}

__device__ __forceinline__ int load_idx(const void* ei, long long pos, int is64) {
    if (is64) return (int)((const long long*)ei)[pos];
    return ((const int*)ei)[pos];
}

// ---------------- dtype detection: int64 vs int32 edge_index -----------------
__global__ void k_detect(const unsigned long long* ei) {
    if (threadIdx.x == 0 && blockIdx.x == 0) {
        int is64 = 1;
        #pragma unroll 1
        for (int i = 0; i < 64; i++)
            if (ei[i] > 0xFFFFFFFFull) is64 = 0;
        g_is64 = is64;
    }
}

// ---------------- degree histogram -------------------------------------------
__global__ void k_zero_deg() {
    int i = blockIdx.x * blockDim.x + threadIdx.x;
    if (i < NN) g_deg[i] = 0;
}

__global__ void k_deg(const void* ei) {
    int e = blockIdx.x * blockDim.x + threadIdx.x;
    if (e < EE) {
        int is64 = g_is64;
        int dst = load_idx(ei, (long long)EE + e, is64);
        atomicAdd(&g_deg[dst], 1);
    }
}

// ---------------- chip-wide 3-phase exclusive scan ---------------------------
// Phase 1: per-block exclusive scan (warp shuffles), block totals to g_bsum.
__global__ void k_scan_local() {
    __shared__ int warp_tot[32];
    int tid = threadIdx.x;
    int i = blockIdx.x * SCAN_BLK + tid;
    int lane = tid & 31, wid = tid >> 5;

    int v = (i < NN) ? g_deg[i] : 0;
    // warp inclusive scan
    int inc = v;
    #pragma unroll
    for (int d = 1; d < 32; d <<= 1) {
        int t = __shfl_up_sync(0xFFFFFFFFu, inc, d);
        if (lane >= d) inc += t;
    }
    if (lane == 31) warp_tot[wid] = inc;
    __syncthreads();
    if (wid == 0) {
        int wv = (lane < 32) ? warp_tot[lane] : 0;
        int winc = wv;
        #pragma unroll
        for (int d = 1; d < 32; d <<= 1) {
            int t = __shfl_up_sync(0xFFFFFFFFu, winc, d);
            if (lane >= d) winc += t;
        }
        warp_tot[lane] = winc - wv;   // exclusive warp base
        if (lane == 31 && blockIdx.x < NBLK) g_bsum[blockIdx.x] = winc;
    }
    __syncthreads();
    if (i < NN) g_off[i] = warp_tot[wid] + inc - v;   // block-local exclusive
}

// Phase 2: exclusive scan of NBLK block sums (one warp, shuffle w/ carry).
__global__ void k_scan_bsum() {
    int lane = threadIdx.x;
    int carry = 0;
    for (int base = 0; base < NBLK; base += 32) {
        int idx = base + lane;
        int v = (idx < NBLK) ? g_bsum[idx] : 0;
        int inc = v;
        #pragma unroll
        for (int d = 1; d < 32; d <<= 1) {
            int t = __shfl_up_sync(0xFFFFFFFFu, inc, d);
            if (lane >= d) inc += t;
        }
        if (idx < NBLK) g_bsum[idx] = carry + inc - v;  // exclusive
        carry += __shfl_sync(0xFFFFFFFFu, inc, 31);
    }
    if (lane == 0) g_off[NN] = EE;
}

// Phase 3: add block base; emit g_off/g_cur/g_inv.
__global__ void k_scan_apply() {
    int i = blockIdx.x * SCAN_BLK + threadIdx.x;
    if (i < NN) {
        int excl = g_off[i] + g_bsum[blockIdx.x];
        g_off[i] = excl;
        g_cur[i] = excl;
        g_inv[i] = 1.0f / (float)max(g_deg[i], 1);
    }
}

// ---------------- CSR placement ----------------------------------------------
__global__ void k_fill(const void* ei) {
    int e = blockIdx.x * blockDim.x + threadIdx.x;
    if (e < EE) {
        int is64 = g_is64;
        int dst = load_idx(ei, (long long)EE + e, is64);
        int src = load_idx(ei, e, is64);
        int pos = atomicAdd(&g_cur[dst], 1);
        g_src[pos] = src;
    }
}

// ---------------- gather aggregation: warp per node, pre-scaled by inv_deg ---
__global__ void k_agg(const float* __restrict__ feat, float* __restrict__ agg) {
    int w = (blockIdx.x * blockDim.x + threadIdx.x) >> 5;
    int lane = threadIdx.x & 31;
    if (w >= NN) return;
    int s = g_off[w], e = g_off[w + 1];
    float4 acc = make_float4(0.f, 0.f, 0.f, 0.f);
    for (int i = s; i < e; i++) {
        int sn = g_src[i];
        float4 v = __ldg((const float4*)(feat + (size_t)sn * 128 + lane * 4));
        acc.x += v.x; acc.y += v.y; acc.z += v.z; acc.w += v.w;
    }
    float iv = g_inv[w];
    acc.x *= iv; acc.y *= iv; acc.z *= iv; acc.w *= iv;
    *((float4*)(agg + (size_t)w * 128 + lane * 4)) = acc;
}

// ---------------- fused SGEMM:  out = [Aagg | Ax] @ [Wl ; Wr] + bias ---------
// K is fixed at 256 (128 from agg side, 128 from x side). BN == ncols.
template <int BM, int BN, int BK, int TM, int TN, bool RELU>
__global__ void __launch_bounds__((BM / TM) * (BN / TN))
k_gemm(const float* __restrict__ Aagg, const float* __restrict__ Ax,
       const float* __restrict__ Wl, const float* __restrict__ Wr,
       const float* __restrict__ bias, float* __restrict__ outp,
       int nrows, int ncols) {
    constexpr int THREADS = (BM / TM) * (BN / TN);
    __shared__ float As[BK][BM];
    __shared__ float Bs[BK][BN];

    const int tid = threadIdx.x;
    const int row0 = blockIdx.x * BM;
    const int tcol = tid % (BN / TN);
    const int trow = tid / (BN / TN);

    unsigned long long acc[TM][TN / 2];
    #pragma unroll
    for (int m = 0; m < TM; m++)
        #pragma unroll
        for (int n = 0; n < TN / 2; n++) acc[m][n] = 0ull;

    #pragma unroll 1
    for (int kt = 0; kt < 256 / BK; kt++) {
        const int k0 = kt * BK;
        const float* Ap = (k0 < 128) ? (Aagg + k0) : (Ax + (k0 - 128));
        const float* Bp = (k0 < 128) ? (Wl + (size_t)k0 * ncols)
                                     : (Wr + (size_t)(k0 - 128) * ncols);
        // load A tile (transpose into As[k][m])
        #pragma unroll
        for (int t = 0; t < (BM * BK / 4) / THREADS; t++) {
            int id = tid + t * THREADS;
            int m = id / (BK / 4);
            int kq = (id % (BK / 4)) * 4;
            int row = row0 + m;
            float4 v = make_float4(0.f, 0.f, 0.f, 0.f);
            if (row < nrows) v = *(const float4*)(Ap + (size_t)row * 128 + kq);
            As[kq + 0][m] = v.x;
            As[kq + 1][m] = v.y;
            As[kq + 2][m] = v.z;
            As[kq + 3][m] = v.w;
        }
        // load B tile
        #pragma unroll
        for (int t = 0; t < (BK * BN / 4) / THREADS; t++) {
            int id = tid + t * THREADS;
            int k = id / (BN / 4);
            int jq = (id % (BN / 4)) * 4;
            *(float4*)&Bs[k][jq] = *(const float4*)(Bp + (size_t)k * ncols + jq);
        }
        __syncthreads();

        #pragma unroll
        for (int kk = 0; kk < BK; kk++) {
            float a[TM];
            #pragma unroll
            for (int i = 0; i < TM / 4; i++)
                *(float4*)&a[i * 4] = *(const float4*)&As[kk][trow * TM + i * 4];
            unsigned long long bq[TN / 2];
            #pragma unroll
            for (int i = 0; i < TN / 2; i++)
                bq[i] = *(const unsigned long long*)&Bs[kk][tcol * TN + i * 2];
            #pragma unroll
            for (int m = 0; m < TM; m++) {
                unsigned long long aa = pack2(a[m], a[m]);
                #pragma unroll
                for (int n = 0; n < TN / 2; n++) fma2(acc[m][n], aa, bq[n]);
            }
        }
        __syncthreads();
    }

    // epilogue: bias (+ relu) + store
    float bv[TN];
    #pragma unroll
    for (int n = 0; n < TN; n++) bv[n] = bias[tcol * TN + n];

    #pragma unroll
    for (int m = 0; m < TM; m++) {
        int row = row0 + trow * TM + m;
        if (row < nrows) {
            float vals[TN];
            #pragma unroll
            for (int n = 0; n < TN / 2; n++)
                unpack2(acc[m][n], vals[2 * n], vals[2 * n + 1]);
            #pragma unroll
            for (int n = 0; n < TN; n++) {
                vals[n] += bv[n];
                if (RELU) vals[n] = fmaxf(vals[n], 0.f);
            }
            #pragma unroll
            for (int n = 0; n < TN / 4; n++)
                *(float4*)(outp + (size_t)row * ncols + tcol * TN + n * 4) =
                    *(float4*)&vals[n * 4];
        }
    }
}

// ---------------- launch ------------------------------------------------------
extern "C" void kernel_launch(void* const* d_in, const int* in_sizes, int n_in,
                              void* d_out, int out_size) {
    const float* x   = (const float*)d_in[0];
    const void*  ei  = d_in[1];
    const float* W1l = (const float*)d_in[2];
    const float* b1  = (const float*)d_in[3];
    const float* W1r = (const float*)d_in[4];
    const float* W2l = (const float*)d_in[5];
    const float* b2  = (const float*)d_in[6];
    const float* W2r = (const float*)d_in[7];
    float* out = (float*)d_out;

    float *agg, *h;
    cudaGetSymbolAddress((void**)&agg, g_agg);
    cudaGetSymbolAddress((void**)&h, g_h);

    k_detect<<<1, 32>>>((const unsigned long long*)ei);
    k_zero_deg<<<(NN + 255) / 256, 256>>>();
    k_deg<<<(EE + 255) / 256, 256>>>(ei);
    k_scan_local<<<NBLK, SCAN_BLK>>>();
    k_scan_bsum<<<1, 32>>>();
    k_scan_apply<<<NBLK, SCAN_BLK>>>();
    k_fill<<<(EE + 255) / 256, 256>>>(ei);

    // layer 1
    k_agg<<<(NN * 32 + 255) / 256, 256>>>(x, agg);
    k_gemm<128, 128, 16, 8, 8, true>
        <<<(NN + 127) / 128, 256>>>(agg, x, W1l, W1r, b1, h, NN, 128);

    // layer 2
    k_agg<<<(NN * 32 + 255) / 256, 256>>>(h, agg);
    k_gemm<128, 32, 32, 8, 4, false>
        <<<(NN + 127) / 128, 128>>>(agg, h, W2l, W2r, b2, out, NN, 32);
}

// round 6
// speedup vs baseline: 2.0256x; 1.4474x over previous
#include <cuda_runtime.h>
#include <cuda_bf16.h>

#define NN 100000
#define EE 600000
#define SCAN_BLK 1024
#define NBLK ((NN + SCAN_BLK - 1) / SCAN_BLK)   // 98

// ---------------- scratch (static device globals; no allocation) -------------
__device__ int   g_deg[NN];
__device__ int   g_off[NN + 1];
__device__ int   g_cur[NN];
__device__ float g_inv[NN];
__device__ int   g_src[EE];
__device__ int   g_bsum[NBLK];
__device__ float g_agg[(size_t)NN * 128];
__device__ float g_h[(size_t)NN * 128];
// weight images, transposed [n][k], bf16, half 0 = hi, half 1 = lo
__device__ __nv_bfloat16 g_w1t[2 * 128 * 256];
__device__ __nv_bfloat16 g_w2t[2 * 32 * 256];
__device__ int   g_is64;

// ---------------- helpers ----------------------------------------------------
__device__ __forceinline__ int load_idx(const void* ei, long long pos, int is64) {
    if (is64) return (int)((const long long*)ei)[pos];
    return ((const int*)ei)[pos];
}
// pack two floats to bf16x2 (a -> low 16 bits, b -> high 16 bits)
__device__ __forceinline__ unsigned cvt_bf16x2(float a, float b) {
    unsigned r;
    asm("cvt.rn.bf16x2.f32 %0, %1, %2;" : "=r"(r) : "f"(b), "f"(a));
    return r;
}
__device__ __forceinline__ void mma16816(float* d, const unsigned* a, const unsigned* b) {
    asm volatile(
        "mma.sync.aligned.m16n8k16.row.col.f32.bf16.bf16.f32 "
        "{%0,%1,%2,%3}, {%4,%5,%6,%7}, {%8,%9}, {%0,%1,%2,%3};"
        : "+f"(d[0]), "+f"(d[1]), "+f"(d[2]), "+f"(d[3])
        : "r"(a[0]), "r"(a[1]), "r"(a[2]), "r"(a[3]), "r"(b[0]), "r"(b[1]));
}

// ---------------- dtype detection: int64 vs int32 edge_index -----------------
__global__ void k_detect(const unsigned long long* ei) {
    if (threadIdx.x == 0 && blockIdx.x == 0) {
        int is64 = 1;
        #pragma unroll 1
        for (int i = 0; i < 64; i++)
            if (ei[i] > 0xFFFFFFFFull) is64 = 0;
        g_is64 = is64;
    }
}

// ---------------- degree histogram -------------------------------------------
__global__ void k_zero_deg() {
    int i = blockIdx.x * blockDim.x + threadIdx.x;
    if (i < NN) g_deg[i] = 0;
}

__global__ void k_deg(const void* ei) {
    int e = blockIdx.x * blockDim.x + threadIdx.x;
    if (e < EE) {
        int is64 = g_is64;
        int dst = load_idx(ei, (long long)EE + e, is64);
        atomicAdd(&g_deg[dst], 1);
    }
}

// ---------------- chip-wide 3-phase exclusive scan ---------------------------
__global__ void k_scan_local() {
    __shared__ int warp_tot[32];
    int tid = threadIdx.x;
    int i = blockIdx.x * SCAN_BLK + tid;
    int lane = tid & 31, wid = tid >> 5;
    int v = (i < NN) ? g_deg[i] : 0;
    int inc = v;
    #pragma unroll
    for (int d = 1; d < 32; d <<= 1) {
        int t = __shfl_up_sync(0xFFFFFFFFu, inc, d);
        if (lane >= d) inc += t;
    }
    if (lane == 31) warp_tot[wid] = inc;
    __syncthreads();
    if (wid == 0) {
        int wv = warp_tot[lane];
        int winc = wv;
        #pragma unroll
        for (int d = 1; d < 32; d <<= 1) {
            int t = __shfl_up_sync(0xFFFFFFFFu, winc, d);
            if (lane >= d) winc += t;
        }
        warp_tot[lane] = winc - wv;
        if (lane == 31) g_bsum[blockIdx.x] = winc;
    }
    __syncthreads();
    if (i < NN) g_off[i] = warp_tot[wid] + inc - v;
}

__global__ void k_scan_bsum() {
    int lane = threadIdx.x;
    int carry = 0;
    for (int base = 0; base < NBLK; base += 32) {
        int idx = base + lane;
        int v = (idx < NBLK) ? g_bsum[idx] : 0;
        int inc = v;
        #pragma unroll
        for (int d = 1; d < 32; d <<= 1) {
            int t = __shfl_up_sync(0xFFFFFFFFu, inc, d);
            if (lane >= d) inc += t;
        }
        if (idx < NBLK) g_bsum[idx] = carry + inc - v;
        carry += __shfl_sync(0xFFFFFFFFu, inc, 31);
    }
    if (lane == 0) g_off[NN] = EE;
}

__global__ void k_scan_apply() {
    int i = blockIdx.x * SCAN_BLK + threadIdx.x;
    if (i < NN) {
        int excl = g_off[i] + g_bsum[blockIdx.x];
        g_off[i] = excl;
        g_cur[i] = excl;
        g_inv[i] = 1.0f / (float)max(g_deg[i], 1);
    }
}

// ---------------- CSR placement ----------------------------------------------
__global__ void k_fill(const void* ei) {
    int e = blockIdx.x * blockDim.x + threadIdx.x;
    if (e < EE) {
        int is64 = g_is64;
        int dst = load_idx(ei, (long long)EE + e, is64);
        int src = load_idx(ei, e, is64);
        int pos = atomicAdd(&g_cur[dst], 1);
        g_src[pos] = src;
    }
}

// ---------------- gather aggregation: warp per node --------------------------
__global__ void k_agg(const float* __restrict__ feat, float* __restrict__ agg) {
    int w = (blockIdx.x * blockDim.x + threadIdx.x) >> 5;
    int lane = threadIdx.x & 31;
    if (w >= NN) return;
    int s = g_off[w], e = g_off[w + 1];
    float4 acc = make_float4(0.f, 0.f, 0.f, 0.f);
    for (int i = s; i < e; i++) {
        int sn = g_src[i];
        float4 v = __ldg((const float4*)(feat + (size_t)sn * 128 + lane * 4));
        acc.x += v.x; acc.y += v.y; acc.z += v.z; acc.w += v.w;
    }
    float iv = g_inv[w];
    acc.x *= iv; acc.y *= iv; acc.z *= iv; acc.w *= iv;
    *((float4*)(agg + (size_t)w * 128 + lane * 4)) = acc;
}

// ---------------- weight prep: transposed bf16 hi/lo images -------------------
// g_wt[half][n*256 + k], k<128 -> Wl[k][n], else Wr[k-128][n]
__global__ void k_prepw(const float* __restrict__ Wl, const float* __restrict__ Wr,
                        __nv_bfloat16* __restrict__ wt, int ncols) {
    int idx = blockIdx.x * blockDim.x + threadIdx.x;
    int total = ncols * 256;
    if (idx >= 2 * total) return;
    int half = idx >= total;
    int rem = half ? idx - total : idx;
    int n = rem >> 8;
    int k = rem & 255;
    float w = (k < 128) ? Wl[k * ncols + n] : Wr[(k - 128) * ncols + n];
    __nv_bfloat16 hi = __float2bfloat16(w);
    __nv_bfloat16 val = half ? __float2bfloat16(w - __bfloat162float(hi)) : hi;
    wt[(size_t)half * total + n * 256 + k] = val;
}

// ---------------- mma.sync bf16 hi/lo split GEMM ------------------------------
// out[r, 0:BN] = [Aagg | Ax](f32) @ Wt^T + bias  (K = 256, 8 chunks of 32)
// Wt: bf16 [2][BN*256] (hi, lo), n-major rows of k.
// smem tiles: b32 rows of 16, padded to stride 20 (conflict-free frag loads).
#define SSTR 20
template <int BM, int BN, int WM, int WN, bool RELU>
__global__ void __launch_bounds__(256)
k_mma(const float* __restrict__ Aagg, const float* __restrict__ Ax,
      const __nv_bfloat16* __restrict__ Wt, const float* __restrict__ bias,
      float* __restrict__ outp) {
    __shared__ unsigned sA[2][BM * SSTR];
    __shared__ unsigned sB[2][BN * SSTR];

    const int tid = threadIdx.x;
    const int wid = tid >> 5, lane = tid & 31;
    const int lr = lane >> 2, lc = lane & 3;
    const int row0 = blockIdx.x * BM;
    constexpr int NWN = BN / WN;              // warps along N
    const int warp_n = wid % NWN;
    const int warp_m = wid / NWN;
    constexpr int MT = WM / 16, NT = WN / 8;  // m/n tiles per warp

    const unsigned* Bt32 = (const unsigned*)Wt;
    constexpr int BHALF = BN * 128;           // b32 offset of lo image

    float acc[MT][NT][4];
    #pragma unroll
    for (int t = 0; t < MT; t++)
        #pragma unroll
        for (int u = 0; u < NT; u++)
            #pragma unroll
            for (int q = 0; q < 4; q++) acc[t][u][q] = 0.f;

    #pragma unroll 1
    for (int kc = 0; kc < 8; kc++) {
        const int k0 = kc * 32;
        // ---- stage A chunk: BM x 32 f32 -> bf16 hi/lo --------------------
        const float* Abase = (k0 < 128) ? (Aagg + k0) : (Ax + (k0 - 128));
        #pragma unroll
        for (int t = 0; t < BM * 32 / 1024; t++) {
            int id = tid + t * 256;
            int row = id >> 3;            // 8 float4 per row
            int c4 = id & 7;
            int rg = row0 + row;
            float4 f = (rg < NN)
                ? __ldg((const float4*)(Abase + (size_t)rg * 128 + c4 * 4))
                : make_float4(0.f, 0.f, 0.f, 0.f);
            float hx = __bfloat162float(__float2bfloat16(f.x));
            float hy = __bfloat162float(__float2bfloat16(f.y));
            float hz = __bfloat162float(__float2bfloat16(f.z));
            float hw = __bfloat162float(__float2bfloat16(f.w));
            int p = row * SSTR + c4 * 2;
            sA[0][p]     = cvt_bf16x2(f.x, f.y);
            sA[0][p + 1] = cvt_bf16x2(f.z, f.w);
            sA[1][p]     = cvt_bf16x2(f.x - hx, f.y - hy);
            sA[1][p + 1] = cvt_bf16x2(f.z - hz, f.w - hw);
        }
        // ---- stage B chunk: BN x 32 bf16 (hi, lo) ------------------------
        #pragma unroll
        for (int id = tid; id < BN * 16; id += 256) {
            int n = id >> 4;
            int j = id & 15;
            int srcp = n * 128 + (k0 >> 1) + j;
            sB[0][n * SSTR + j] = __ldg(&Bt32[srcp]);
            sB[1][n * SSTR + j] = __ldg(&Bt32[BHALF + srcp]);
        }
        __syncthreads();

        // ---- compute: 2 k16 steps x 3 products ---------------------------
        #pragma unroll
        for (int kh = 0; kh < 2; kh++) {
            const int base = kh * 8;
            unsigned ah[MT][4], al[MT][4];
            #pragma unroll
            for (int t = 0; t < MT; t++) {
                int r = warp_m * WM + t * 16 + lr;
                int p0 = r * SSTR + base + lc;
                int p1 = (r + 8) * SSTR + base + lc;
                ah[t][0] = sA[0][p0]; ah[t][1] = sA[0][p1];
                ah[t][2] = sA[0][p0 + 4]; ah[t][3] = sA[0][p1 + 4];
                al[t][0] = sA[1][p0]; al[t][1] = sA[1][p1];
                al[t][2] = sA[1][p0 + 4]; al[t][3] = sA[1][p1 + 4];
            }
            unsigned bh[NT][2], bl[NT][2];
            #pragma unroll
            for (int u = 0; u < NT; u++) {
                int n = warp_n * WN + u * 8 + lr;
                int p = n * SSTR + base + lc;
                bh[u][0] = sB[0][p]; bh[u][1] = sB[0][p + 4];
                bl[u][0] = sB[1][p]; bl[u][1] = sB[1][p + 4];
            }
            #pragma unroll
            for (int t = 0; t < MT; t++)
                #pragma unroll
                for (int u = 0; u < NT; u++) {
                    mma16816(acc[t][u], ah[t], bh[u]);
                    mma16816(acc[t][u], al[t], bh[u]);
                    mma16816(acc[t][u], ah[t], bl[u]);
                }
        }
        __syncthreads();
    }

    // ---- epilogue -----------------------------------------------------------
    #pragma unroll
    for (int t = 0; t < MT; t++) {
        int r = row0 + warp_m * WM + t * 16 + lr;
        #pragma unroll
        for (int u = 0; u < NT; u++) {
            int c = warp_n * WN + u * 8 + lc * 2;
            float b0 = __ldg(&bias[c]), b1 = __ldg(&bias[c + 1]);
            float v0 = acc[t][u][0] + b0, v1 = acc[t][u][1] + b1;
            float v2 = acc[t][u][2] + b0, v3 = acc[t][u][3] + b1;
            if (RELU) {
                v0 = fmaxf(v0, 0.f); v1 = fmaxf(v1, 0.f);
                v2 = fmaxf(v2, 0.f); v3 = fmaxf(v3, 0.f);
            }
            if (r < NN)
                *(float2*)(outp + (size_t)r * BN + c) = make_float2(v0, v1);
            if (r + 8 < NN)
                *(float2*)(outp + (size_t)(r + 8) * BN + c) = make_float2(v2, v3);
        }
    }
}

// ---------------- launch ------------------------------------------------------
extern "C" void kernel_launch(void* const* d_in, const int* in_sizes, int n_in,
                              void* d_out, int out_size) {
    const float* x   = (const float*)d_in[0];
    const void*  ei  = d_in[1];
    const float* W1l = (const float*)d_in[2];
    const float* b1  = (const float*)d_in[3];
    const float* W1r = (const float*)d_in[4];
    const float* W2l = (const float*)d_in[5];
    const float* b2  = (const float*)d_in[6];
    const float* W2r = (const float*)d_in[7];
    float* out = (float*)d_out;

    float *agg, *h;
    __nv_bfloat16 *w1t, *w2t;
    cudaGetSymbolAddress((void**)&agg, g_agg);
    cudaGetSymbolAddress((void**)&h, g_h);
    cudaGetSymbolAddress((void**)&w1t, g_w1t);
    cudaGetSymbolAddress((void**)&w2t, g_w2t);

    k_detect<<<1, 32>>>((const unsigned long long*)ei);
    k_zero_deg<<<(NN + 255) / 256, 256>>>();
    k_prepw<<<(2 * 128 * 256 + 255) / 256, 256>>>(W1l, W1r, w1t, 128);
    k_prepw<<<(2 * 32 * 256 + 255) / 256, 256>>>(W2l, W2r, w2t, 32);
    k_deg<<<(EE + 255) / 256, 256>>>(ei);
    k_scan_local<<<NBLK, SCAN_BLK>>>();
    k_scan_bsum<<<1, 32>>>();
    k_scan_apply<<<NBLK, SCAN_BLK>>>();
    k_fill<<<(EE + 255) / 256, 256>>>(ei);

    // layer 1: agg + tensor GEMM (bf16 hi/lo split) + relu
    k_agg<<<(NN * 32 + 255) / 256, 256>>>(x, agg);
    k_mma<128, 128, 32, 64, true>
        <<<(NN + 127) / 128, 256>>>(agg, x, w1t, b1, h);

    // layer 2: agg + tensor GEMM
    k_agg<<<(NN * 32 + 255) / 256, 256>>>(h, agg);
    k_mma<256, 32, 32, 32, false>
        <<<(NN + 255) / 256, 256>>>(agg, h, w2t, b2, out);
}